// round 5
// baseline (speedup 1.0000x reference)
#include <cuda_runtime.h>
#include <cuda_bf16.h>

// Inverse of f(x) = a*x + (1-a)*softplus(x), a = 0.1 + 0.4*sigmoid(raw_alpha).
//
// R5: 2 Halley iterations; softplus's log replaced by a degree-7 Chebyshev-
// economized polynomial in u = 2e-1 (e = exp(-|x|) in (0,1]):
//   ln(1+e) = ln(3+u) - ln2 ~= A0 + A1 u + ... + A7 u^7,  |err| <~ 1e-6
// evaluated entirely with packed fma.rn.f32x2. MUFU count drops 6 -> 4 per
// element (EX2 + RCP per iteration); the log moves onto the FMA pipe where
// issue slots were idle. Loads/stores use streaming (.cs) hints (touch-once).

#define LN2F   0.6931471805599453f
#define L2EF   1.4426950408889634f

typedef unsigned long long ull;

__device__ __forceinline__ ull pack2(float lo, float hi) {
    ull r; asm("mov.b64 %0, {%1, %2};" : "=l"(r) : "f"(lo), "f"(hi)); return r;
}
__device__ __forceinline__ void unpack2(ull v, float& lo, float& hi) {
    asm("mov.b64 {%0, %1}, %2;" : "=f"(lo), "=f"(hi) : "l"(v));
}
__device__ __forceinline__ ull fma2(ull a, ull b, ull c) {
    ull d; asm("fma.rn.f32x2 %0, %1, %2, %3;" : "=l"(d) : "l"(a), "l"(b), "l"(c)); return d;
}
__device__ __forceinline__ ull mul2(ull a, ull b) {
    ull d; asm("mul.rn.f32x2 %0, %1, %2;" : "=l"(d) : "l"(a), "l"(b)); return d;
}
__device__ __forceinline__ ull add2(ull a, ull b) {
    ull d; asm("add.rn.f32x2 %0, %1, %2;" : "=l"(d) : "l"(a), "l"(b)); return d;
}
__device__ __forceinline__ float rcp_approx(float x) {
    float r; asm("rcp.approx.ftz.f32 %0, %1;" : "=f"(r) : "f"(x)); return r;
}
__device__ __forceinline__ float ex2_approx(float x) {
    float r; asm("ex2.approx.ftz.f32 %0, %1;" : "=f"(r) : "f"(x)); return r;
}
__device__ __forceinline__ float lg2_approx(float x) {
    float r; asm("lg2.approx.ftz.f32 %0, %1;" : "=f"(r) : "f"(x)); return r;
}

// ln(3+u) - ln2 on u in [-1,1]; Chebyshev-economized (rho = 3+sqrt(8)).
#define PA0  0.40546587f
#define PA1  0.33333308f
#define PA2 -0.05556128f
#define PA3  0.01234897f
#define PA4 -0.00305813f
#define PA5  0.00081148f
#define PA6 -0.00027210f
#define PA7  0.00008003f

struct Consts {
    ull k2;      // splat(inv_a - 1)
    ull negc2;   // splat(-(1-a)*ln2)
    ull a2, na2, oma2, noma2, omah2;
    ull one2, two2, negone2;
    ull A0, A1, A2, A3, A4, A5, A6, A7;
    float a, oma, omah, inv_a, c;  // scalar copies for the tail path
};

// Packed 2-iteration Halley solve for a lane pair packed in Y.
__device__ __forceinline__ ull halley_pair(ull Y, const Consts& C) {
    float y0, y1; unpack2(Y, y0, y1);
    // x0 = y + min(y,0)*(1/a - 1) - (1-a)*ln2
    ull M = pack2(fminf(y0, 0.0f), fminf(y1, 0.0f));
    ull X = fma2(M, C.k2, add2(Y, C.negc2));
#pragma unroll
    for (int it = 0; it < 2; ++it) {
        float x0, x1; unpack2(X, x0, x1);
        float e0 = ex2_approx(-fabsf(x0) * L2EF);        // MUFU EX2
        float e1 = ex2_approx(-fabsf(x1) * L2EF);
        ull  E  = pack2(e0, e1);
        ull  D  = add2(E, C.one2);                       // d = 1+e
        // log1p(e) via packed Horner in u = 2e-1
        ull  U  = fma2(E, C.two2, C.negone2);
        ull  H  = fma2(C.A7, U, C.A6);
        H = fma2(H, U, C.A5);
        H = fma2(H, U, C.A4);
        H = fma2(H, U, C.A3);
        H = fma2(H, U, C.A2);
        H = fma2(H, U, C.A1);
        H = fma2(H, U, C.A0);                            // ~= ln(1+e)
        ull  SP = add2(H, pack2(fmaxf(x0, 0.0f), fmaxf(x1, 0.0f)));
        ull  G  = fma2(C.noma2, SP, fma2(C.na2, X, Y));  // y - f(x)
        ull  S  = pack2((x0 > 0.0f) ? 1.0f : e0,
                        (x1 > 0.0f) ? 1.0f : e1);
        ull  P  = fma2(C.a2, D, mul2(C.oma2, S));        // d * f'(x)
        ull  DEN = fma2(P, P, mul2(G, mul2(C.omah2, E)));// P^2 - ft*(1-a)e/2 > 0
        float dn0, dn1; unpack2(DEN, dn0, dn1);
        ull  R  = pack2(rcp_approx(dn0), rcp_approx(dn1)); // MUFU RCP
        ull  GPD = mul2(G, mul2(P, D));                  // -ft*P*d
        X = fma2(GPD, R, X);
    }
    return X;
}

// Scalar fallback for tail elements (uses exact MUFU log — accuracy identical).
__device__ __forceinline__ float halley_scalar(float y, const Consts& C) {
    float x = ((y > 0.0f) ? y : y * C.inv_a) - C.c;
#pragma unroll
    for (int it = 0; it < 2; ++it) {
        float e  = ex2_approx(-fabsf(x) * L2EF);
        float d  = 1.0f + e;
        float sp = fmaf(LN2F, lg2_approx(d), fmaxf(x, 0.0f));
        float g  = fmaf(-C.oma, sp, fmaf(-C.a, x, y));
        float s  = (x > 0.0f) ? 1.0f : e;
        float P  = fmaf(C.a, d, C.oma * s);
        float den = fmaf(P, P, g * (C.omah * e));
        x = fmaf(g * (P * d), rcp_approx(den), x);
    }
    return x;
}

__device__ __forceinline__ float4 ldcs4(const float4* p) {
    float4 v;
    asm("ld.global.cs.v4.f32 {%0,%1,%2,%3}, [%4];"
        : "=f"(v.x), "=f"(v.y), "=f"(v.z), "=f"(v.w) : "l"(p));
    return v;
}
__device__ __forceinline__ void stcs4(float4* p, float4 v) {
    asm("st.global.cs.v4.f32 [%0], {%1,%2,%3,%4};"
        :: "l"(p), "f"(v.x), "f"(v.y), "f"(v.z), "f"(v.w) : "memory");
}

__global__ __launch_bounds__(256)
void inv_leaky_softplus_kernel(const float4* __restrict__ in,
                               const float* __restrict__ raw_alpha,
                               float4* __restrict__ out,
                               int n4, int n_rem,
                               const float* __restrict__ rem_in,
                               float* __restrict__ rem_out) {
    float ra  = raw_alpha[0];
    float a   = fmaf(0.4f, rcp_approx(1.0f + ex2_approx(-ra * L2EF)), 0.1f);
    float oma = 1.0f - a;
    float iva = rcp_approx(a);
    iva = iva * (2.0f - a * iva);    // refine reciprocal to full precision

    Consts C;
    C.a = a; C.oma = oma; C.omah = 0.5f * oma; C.inv_a = iva; C.c = oma * LN2F;
    C.k2      = pack2(iva - 1.0f, iva - 1.0f);
    C.negc2   = pack2(-C.c, -C.c);
    C.a2      = pack2(a, a);
    C.na2     = pack2(-a, -a);
    C.oma2    = pack2(oma, oma);
    C.noma2   = pack2(-oma, -oma);
    C.omah2   = pack2(C.omah, C.omah);
    C.one2    = pack2(1.0f, 1.0f);
    C.two2    = pack2(2.0f, 2.0f);
    C.negone2 = pack2(-1.0f, -1.0f);
    C.A0 = pack2(PA0, PA0); C.A1 = pack2(PA1, PA1);
    C.A2 = pack2(PA2, PA2); C.A3 = pack2(PA3, PA3);
    C.A4 = pack2(PA4, PA4); C.A5 = pack2(PA5, PA5);
    C.A6 = pack2(PA6, PA6); C.A7 = pack2(PA7, PA7);

    int i = blockIdx.x * blockDim.x + threadIdx.x;
    if (i < n4) {
        float4 y4 = ldcs4(in + i);
        ull X01 = halley_pair(pack2(y4.x, y4.y), C);
        ull X23 = halley_pair(pack2(y4.z, y4.w), C);
        float4 x4;
        unpack2(X01, x4.x, x4.y);
        unpack2(X23, x4.z, x4.w);
        stcs4(out + i, x4);
    }
    if (i < n_rem) {
        rem_out[i] = halley_scalar(rem_in[i], C);
    }
}

extern "C" void kernel_launch(void* const* d_in, const int* in_sizes, int n_in,
                              void* d_out, int out_size) {
    const float* inp   = (const float*)d_in[0];
    const float* alpha = (const float*)d_in[1];
    float*       outp  = (float*)d_out;

    int n     = in_sizes[0];
    int n4    = n >> 2;
    int n_rem = n & 3;
    const float* rem_in  = inp  + (size_t)n4 * 4;
    float*       rem_out = outp + (size_t)n4 * 4;

    int threads = 256;
    int work    = (n4 > n_rem) ? n4 : n_rem;
    int blocks  = (work + threads - 1) / threads;
    if (blocks < 1) blocks = 1;

    inv_leaky_softplus_kernel<<<blocks, threads>>>(
        (const float4*)inp, alpha, (float4*)outp, n4, n_rem, rem_in, rem_out);
}

// round 7
// speedup vs baseline: 1.3973x; 1.3973x over previous
#include <cuda_runtime.h>
#include <cuda_bf16.h>

// Inverse of f(x) = a*x + (1-a)*softplus(x), a = 0.1 + 0.4*sigmoid(raw_alpha).
//
// R6: exact R4 math (2 Halley iterations, MUFU EX2/LG2/RCP, f32x2-packed FMA
// pipe work), but 8 elements per thread = 4 independent pair-chains to hide
// MUFU latency (R5 post-mortem: kernel is dependency-bound, not MUFU-
// throughput-bound). Two float4 loads issued up front for MLP.

#define LN2F   0.6931471805599453f
#define L2EF   1.4426950408889634f

typedef unsigned long long ull;

__device__ __forceinline__ ull pack2(float lo, float hi) {
    ull r; asm("mov.b64 %0, {%1, %2};" : "=l"(r) : "f"(lo), "f"(hi)); return r;
}
__device__ __forceinline__ void unpack2(ull v, float& lo, float& hi) {
    asm("mov.b64 {%0, %1}, %2;" : "=f"(lo), "=f"(hi) : "l"(v));
}
__device__ __forceinline__ ull fma2(ull a, ull b, ull c) {
    ull d; asm("fma.rn.f32x2 %0, %1, %2, %3;" : "=l"(d) : "l"(a), "l"(b), "l"(c)); return d;
}
__device__ __forceinline__ ull mul2(ull a, ull b) {
    ull d; asm("mul.rn.f32x2 %0, %1, %2;" : "=l"(d) : "l"(a), "l"(b)); return d;
}
__device__ __forceinline__ ull add2(ull a, ull b) {
    ull d; asm("add.rn.f32x2 %0, %1, %2;" : "=l"(d) : "l"(a), "l"(b)); return d;
}
__device__ __forceinline__ float rcp_approx(float x) {
    float r; asm("rcp.approx.ftz.f32 %0, %1;" : "=f"(r) : "f"(x)); return r;
}
__device__ __forceinline__ float ex2_approx(float x) {
    float r; asm("ex2.approx.ftz.f32 %0, %1;" : "=f"(r) : "f"(x)); return r;
}
__device__ __forceinline__ float lg2_approx(float x) {
    float r; asm("lg2.approx.ftz.f32 %0, %1;" : "=f"(r) : "f"(x)); return r;
}

struct Consts {
    ull k2;      // splat(inv_a - 1)
    ull negc2;   // splat(-(1-a)*ln2)
    ull one2;    // splat(1.0)
    ull ln2_2;   // splat(ln2)
    ull a2, na2, oma2, noma2, omah2;
    float a, oma, omah, inv_a, c;   // scalar copies for the tail path
};

// Packed 2-iteration Halley solve for a lane pair packed in Y.
__device__ __forceinline__ ull halley_pair(ull Y, const Consts& C) {
    float y0, y1; unpack2(Y, y0, y1);
    // x0 = y + min(y,0)*(1/a - 1) - (1-a)*ln2
    ull M = pack2(fminf(y0, 0.0f), fminf(y1, 0.0f));
    ull X = fma2(M, C.k2, add2(Y, C.negc2));
#pragma unroll
    for (int it = 0; it < 2; ++it) {
        float x0, x1; unpack2(X, x0, x1);
        float e0 = ex2_approx(-fabsf(x0) * L2EF);        // MUFU EX2
        float e1 = ex2_approx(-fabsf(x1) * L2EF);
        ull  E  = pack2(e0, e1);
        ull  D  = add2(E, C.one2);                       // d = 1+e
        float d0, d1; unpack2(D, d0, d1);
        float l0 = lg2_approx(d0);                       // MUFU LG2
        float l1 = lg2_approx(d1);
        ull  SP = fma2(pack2(l0, l1), C.ln2_2,
                       pack2(fmaxf(x0, 0.0f), fmaxf(x1, 0.0f)));  // softplus
        ull  G  = fma2(C.noma2, SP, fma2(C.na2, X, Y));  // y - f(x)
        ull  S  = pack2((x0 > 0.0f) ? 1.0f : e0,
                        (x1 > 0.0f) ? 1.0f : e1);
        ull  P  = fma2(C.a2, D, mul2(C.oma2, S));        // d * f'(x)
        ull  DEN = fma2(P, P, mul2(G, mul2(C.omah2, E)));// P^2 - ft*(1-a)e/2 > 0
        float dn0, dn1; unpack2(DEN, dn0, dn1);
        ull  R  = pack2(rcp_approx(dn0), rcp_approx(dn1)); // MUFU RCP
        ull  GPD = mul2(G, mul2(P, D));                  // -ft*P*d
        X = fma2(GPD, R, X);
    }
    return X;
}

// Scalar path for tail elements.
__device__ __forceinline__ float halley_scalar(float y, const Consts& C) {
    float x = ((y > 0.0f) ? y : y * C.inv_a) - C.c;
#pragma unroll
    for (int it = 0; it < 2; ++it) {
        float e  = ex2_approx(-fabsf(x) * L2EF);
        float d  = 1.0f + e;
        float sp = fmaf(LN2F, lg2_approx(d), fmaxf(x, 0.0f));
        float g  = fmaf(-C.oma, sp, fmaf(-C.a, x, y));
        float s  = (x > 0.0f) ? 1.0f : e;
        float P  = fmaf(C.a, d, C.oma * s);
        float den = fmaf(P, P, g * (C.omah * e));
        x = fmaf(g * (P * d), rcp_approx(den), x);
    }
    return x;
}

__device__ __forceinline__ float4 solve4(float4 y4, const Consts& C) {
    ull X01 = halley_pair(pack2(y4.x, y4.y), C);
    ull X23 = halley_pair(pack2(y4.z, y4.w), C);
    float4 x4;
    unpack2(X01, x4.x, x4.y);
    unpack2(X23, x4.z, x4.w);
    return x4;
}

__global__ __launch_bounds__(256)
void inv_leaky_softplus_kernel(const float4* __restrict__ in,
                               const float* __restrict__ raw_alpha,
                               float4* __restrict__ out,
                               int n4, int half_stride, int n_rem,
                               const float* __restrict__ rem_in,
                               float* __restrict__ rem_out) {
    float ra  = raw_alpha[0];
    float a   = fmaf(0.4f, rcp_approx(1.0f + ex2_approx(-ra * L2EF)), 0.1f);
    float oma = 1.0f - a;
    float iva = rcp_approx(a);
    iva = iva * (2.0f - a * iva);    // refine reciprocal to full precision

    Consts C;
    C.a = a; C.oma = oma; C.omah = 0.5f * oma; C.inv_a = iva; C.c = oma * LN2F;
    C.k2    = pack2(iva - 1.0f, iva - 1.0f);
    C.negc2 = pack2(-C.c, -C.c);
    C.one2  = pack2(1.0f, 1.0f);
    C.ln2_2 = pack2(LN2F, LN2F);
    C.a2    = pack2(a, a);
    C.na2   = pack2(-a, -a);
    C.oma2  = pack2(oma, oma);
    C.noma2 = pack2(-oma, -oma);
    C.omah2 = pack2(C.omah, C.omah);

    int i  = blockIdx.x * blockDim.x + threadIdx.x;   // first float4
    int j  = i + half_stride;                          // second float4

    bool doA = (i < n4);
    bool doB = (j < n4) && (i < half_stride);

    float4 ya, yb;
    if (doA) ya = in[i];           // both loads issued before any compute (MLP)
    if (doB) yb = in[j];

    if (doA) {
        float4 xa = solve4(ya, C); // 2 independent pair-chains
        out[i] = xa;
    }
    if (doB) {
        float4 xb = solve4(yb, C); // 2 more independent pair-chains
        out[j] = xb;
    }

    if (i < n_rem) {
        rem_out[i] = halley_scalar(rem_in[i], C);
    }
}

extern "C" void kernel_launch(void* const* d_in, const int* in_sizes, int n_in,
                              void* d_out, int out_size) {
    const float* inp   = (const float*)d_in[0];
    const float* alpha = (const float*)d_in[1];
    float*       outp  = (float*)d_out;

    int n     = in_sizes[0];
    int n4    = n >> 2;
    int n_rem = n & 3;
    const float* rem_in  = inp  + (size_t)n4 * 4;
    float*       rem_out = outp + (size_t)n4 * 4;

    int half = (n4 + 1) >> 1;            // float4s handled by the "A" slot
    int threads = 256;
    int work = (half > n_rem) ? half : n_rem;
    int blocks = (work + threads - 1) / threads;
    if (blocks < 1) blocks = 1;

    inv_leaky_softplus_kernel<<<blocks, threads>>>(
        (const float4*)inp, alpha, (float4*)outp, n4, half, n_rem, rem_in, rem_out);
}